// round 13
// baseline (speedup 1.0000x reference)
#include <cuda_runtime.h>
#include <cuda_fp16.h>
#include <cstdint>

namespace {
constexpr int BM = 128, BN = 64, DIM = 128;   // 4 warps x m=32 per warp
constexpr int NTHREADS = 128;
constexpr int HEADS = 32, KVH = 8, REP = HEADS / KVH;
constexpr int LD = 136;      // fp16 elems per smem row: 272B stride, conflict-free ldmatrix
constexpr int ROWB = LD * 2; // 272
constexpr float SCALE = 0.088388347648318447f;  // 1/sqrt(128)

constexpr int MAXT = 8192;

// smem: two buffers of [KH, VH]; Q (128 x 272B = 34816 B) staged through buffer 1
constexpr int TILEB = BN * ROWB;       // 17408
constexpr int BUFSZ = 2 * TILEB;       // 34816
constexpr int SMEM_TOTAL = 2 * BUFSZ;  // 69632 -> 2 CTAs/SM (139264 B)
}  // namespace

// persistent fp16 K/V (elem-pairs as uint32: low 16 = even elem)
__device__ uint32_t g_kh[MAXT * KVH * DIM / 2];
__device__ uint32_t g_vh[MAXT * KVH * DIM / 2];

__device__ __forceinline__ uint32_t smem_u32(const void* p) {
  uint32_t a;
  asm("{ .reg .u64 t; cvta.to.shared.u64 t, %1; cvt.u32.u64 %0, t; }" : "=r"(a) : "l"(p));
  return a;
}
__device__ __forceinline__ uint32_t cvt_h2(float a, float b) {
  uint32_t h;
  asm("cvt.rn.f16x2.f32 %0, %1, %2;" : "=r"(h) : "f"(b), "f"(a));  // low16=a, high16=b
  return h;
}
__device__ __forceinline__ void ldsm4(uint32_t a, uint32_t& r0, uint32_t& r1,
                                      uint32_t& r2, uint32_t& r3) {
  asm volatile("ldmatrix.sync.aligned.m8n8.x4.shared.b16 {%0,%1,%2,%3}, [%4];"
               : "=r"(r0), "=r"(r1), "=r"(r2), "=r"(r3) : "r"(a));
}
__device__ __forceinline__ void ldsm4t(uint32_t a, uint32_t& r0, uint32_t& r1,
                                       uint32_t& r2, uint32_t& r3) {
  asm volatile("ldmatrix.sync.aligned.m8n8.x4.trans.shared.b16 {%0,%1,%2,%3}, [%4];"
               : "=r"(r0), "=r"(r1), "=r"(r2), "=r"(r3) : "r"(a));
}
__device__ __forceinline__ void mma_f16(float* c, const uint32_t* a, uint32_t b0,
                                        uint32_t b1) {
  asm volatile(
      "mma.sync.aligned.m16n8k16.row.col.f32.f16.f16.f32 "
      "{%0,%1,%2,%3}, {%4,%5,%6,%7}, {%8,%9}, {%0,%1,%2,%3};"
      : "+f"(c[0]), "+f"(c[1]), "+f"(c[2]), "+f"(c[3])
      : "r"(a[0]), "r"(a[1]), "r"(a[2]), "r"(a[3]), "r"(b0), "r"(b1));
}
__device__ __forceinline__ void cp16(uint32_t dst, const uint32_t* src) {
  asm volatile(
      "{ .reg .u64 g; cvta.to.global.u64 g, %1; cp.async.cg.shared.global [%0], [g], 16; }"
      ::"r"(dst), "l"(src) : "memory");
}
#define CP_COMMIT() asm volatile("cp.async.commit_group;" ::: "memory")
#define CP_WAIT(n) asm volatile("cp.async.wait_group %0;" ::"n"(n) : "memory")

// ---------------- pre-pass: convert K and V to fp16 -------------------------
__global__ void conv_kv_kernel(const float4* __restrict__ k4,
                               const float4* __restrict__ v4, int n4) {
  int i = blockIdx.x * blockDim.x + threadIdx.x;
  if (i >= n4) return;
  float4 kv = k4[i], vv = v4[i];
  g_kh[i * 2] = cvt_h2(kv.x, kv.y);
  g_kh[i * 2 + 1] = cvt_h2(kv.z, kv.w);
  g_vh[i * 2] = cvt_h2(vv.x, vv.y);
  g_vh[i * 2 + 1] = cvt_h2(vv.z, vv.w);
}

// ---------------- main flash-attention kernel -------------------------------
__global__ __launch_bounds__(NTHREADS, 2)
void fa_hmma_kernel(const float* __restrict__ q, const int* __restrict__ cu,
                    float* __restrict__ out, int T, int B) {
  extern __shared__ __align__(16) char smem[];
  const uint32_t smb = smem_u32(smem);
  const int tid = threadIdx.x, lane = tid & 31, wid = tid >> 5;
  const int g = lane >> 2, t = lane & 3;
  const int q0 = blockIdx.x * BM, h = blockIdx.y, hk = h / REP;
  const int wrow = wid * 32;  // 32 q-rows per warp (two m16 tiles)

  // ---- per-thread row bounds (4 rows: mt{0,1} x {g, g+8}) ----------------------
  int rr[2][2];
  int rs[2][2] = {{0, 0}, {0, 0}};   // FIX: was uninitialized in R12
  int hb[2][2] = {{-1, -1}, {-1, -1}};
  int kv_lo = 0;
#pragma unroll
  for (int mt = 0; mt < 2; mt++) {
    rr[mt][0] = q0 + wrow + mt * 16 + g;
    rr[mt][1] = rr[mt][0] + 8;
  }
  for (int b = 1; b <= B; b++) {
    int e = cu[b];
#pragma unroll
    for (int mt = 0; mt < 2; mt++) {
#pragma unroll
      for (int i = 0; i < 2; i++)
        if (rr[mt][i] >= e) rs[mt][i] = e;
    }
    if (q0 >= e) kv_lo = e;
  }
#pragma unroll
  for (int mt = 0; mt < 2; mt++)
#pragma unroll
    for (int i = 0; i < 2; i++) hb[mt][i] = (rr[mt][i] < T) ? rr[mt][i] : -1;
  const int kv_hi = min(q0 + BM, T);

  // staging decomposition: 16 cp16/thread per 64-row tile (K and V)
  const int sc = tid & 15, srh = tid >> 4;  // srh in 0..7

  auto stage = [&](int c0, int buf) {
    uint32_t dbase = smb + buf * BUFSZ;
#pragma unroll
    for (int i = 0; i < 16; i++) {
      int a = i >> 3;
      int r = (i & 7) * 8 + srh;
      const uint32_t* src =
          (a ? g_vh : g_kh) + ((size_t)(c0 + r) * KVH + hk) * (DIM / 2) + sc * 4;
      cp16(dbase + a * TILEB + (uint32_t)r * ROWB + sc * 16, src);
    }
    CP_COMMIT();
  };

  // ---- prefetch tile 0 into buf0; stage Q via buf1; hoist Q frags to regs -------
  stage(kv_lo, 0);

  const float4* q4 = reinterpret_cast<const float4*>(q);
#pragma unroll
  for (int it = 0; it < 32; it++) {
    int idx = it * NTHREADS + tid;
    int row = idx >> 5, c4 = idx & 31;
    float4 val = make_float4(0.f, 0.f, 0.f, 0.f);
    int gr = q0 + row;
    if (gr < T) val = q4[((size_t)gr * HEADS + h) * 32 + c4];
    uint32_t hi0 = cvt_h2(val.x * SCALE, val.y * SCALE);
    uint32_t hi1 = cvt_h2(val.z * SCALE, val.w * SCALE);
    uint32_t off = (uint32_t)row * ROWB + c4 * 8;
    *reinterpret_cast<uint2*>(smem + BUFSZ + off) = make_uint2(hi0, hi1);
  }
  __syncthreads();

  uint32_t qh[2][8][4];
#pragma unroll
  for (int mt = 0; mt < 2; mt++) {
    const uint32_t qstg =
        smb + BUFSZ +
        ((uint32_t)(wrow + mt * 16 + (lane & 7) + (((lane >> 3) & 1) << 3)) * ROWB) +
        ((lane >> 4) << 4);
#pragma unroll
    for (int kt = 0; kt < 8; kt++)
      ldsm4(qstg + kt * 32, qh[mt][kt][0], qh[mt][kt][1], qh[mt][kt][2], qh[mt][kt][3]);
  }

  // ---- ldmatrix per-thread base offsets for K/V ----------------------------------
  const uint32_t krow = ((uint32_t)((lane & 7) + ((lane >> 4) << 3)) * ROWB) +
                        (((lane >> 3) & 1) << 4);
  const uint32_t vrow = ((uint32_t)((lane & 7) + (((lane >> 3) & 1) << 3)) * ROWB) +
                        ((lane >> 4) << 4);

  float O[2][16][4];
#pragma unroll
  for (int mt = 0; mt < 2; mt++)
#pragma unroll
    for (int i = 0; i < 16; i++)
#pragma unroll
      for (int j = 0; j < 4; j++) O[mt][i][j] = 0.f;
  float l[2][2] = {{0.f, 0.f}, {0.f, 0.f}};

  int bi = 0;
  for (int c0 = kv_lo; c0 < kv_hi; c0 += BN, bi++) {
    const int buf = bi & 1;
    const bool has_next = (c0 + BN) < kv_hi;

    __syncthreads();  // readers of buf^1 done (bi=0: Q frag reads done)
    if (has_next) { stage(c0 + BN, buf ^ 1); CP_WAIT(1); }
    else          { CP_WAIT(0); }
    __syncthreads();  // current buffer visible to all warps

    const uint32_t bb = smb + buf * BUFSZ;
    const uint32_t kbase = bb + krow;
    const uint32_t vbase = bb + TILEB + vrow;

    // warp-uniform fast path: all rows valid, tile fully inside causal window
    const bool safe = (rr[1][1] < T) && (c0 >= rs[1][1]) && (c0 + BN <= rr[0][0] + 1);
    const bool allsafe = __all_sync(0xffffffffu, safe);

    // ---- fused per-16-kv-chunk pipeline: QK -> exp -> PV ---------------------------
#pragma unroll
    for (int nt2 = 0; nt2 < 4; nt2++) {
      // S = Q K^T for 16 kv cols, both m-tiles (K frag shared across mt)
      float S[2][2][4];
#pragma unroll
      for (int mt = 0; mt < 2; mt++)
#pragma unroll
        for (int sb = 0; sb < 2; sb++)
#pragma unroll
          for (int j = 0; j < 4; j++) S[mt][sb][j] = 0.f;
#pragma unroll
      for (int kt = 0; kt < 8; kt++) {
        uint32_t bh0, bh1, bh2, bh3;
        uint32_t koff = (uint32_t)nt2 * (16 * ROWB) + kt * 32;
        ldsm4(kbase + koff, bh0, bh1, bh2, bh3);
        mma_f16(S[0][0], qh[0][kt], bh0, bh1);
        mma_f16(S[1][0], qh[1][kt], bh0, bh1);
        mma_f16(S[0][1], qh[0][kt], bh2, bh3);
        mma_f16(S[1][1], qh[1][kt], bh2, bh3);
      }

      // softmax chunk: exp, mask, round to fp16 A-frags; l-sums from ROUNDED values
      uint32_t PhF[2][4];
      if (allsafe) {
#pragma unroll
        for (int mt = 0; mt < 2; mt++)
#pragma unroll
          for (int sb = 0; sb < 2; sb++) {
            float p0 = __expf(S[mt][sb][0]);
            float p1 = __expf(S[mt][sb][1]);
            float p2 = __expf(S[mt][sb][2]);
            float p3 = __expf(S[mt][sb][3]);
            uint32_t h01 = cvt_h2(p0, p1), h23 = cvt_h2(p2, p3);
            PhF[mt][sb * 2 + 0] = h01;
            PhF[mt][sb * 2 + 1] = h23;
            float2 f01 = __half22float2(*reinterpret_cast<__half2*>(&h01));
            float2 f23 = __half22float2(*reinterpret_cast<__half2*>(&h23));
            l[mt][0] += f01.x + f01.y;
            l[mt][1] += f23.x + f23.y;
          }
      } else {
#pragma unroll
        for (int mt = 0; mt < 2; mt++)
#pragma unroll
          for (int sb = 0; sb < 2; sb++) {
            int cb = c0 + 16 * nt2 + 8 * sb + 2 * t;
            float p0 = (cb >= rs[mt][0] && cb <= hb[mt][0]) ? __expf(S[mt][sb][0]) : 0.f;
            float p1 = (cb + 1 >= rs[mt][0] && cb + 1 <= hb[mt][0]) ? __expf(S[mt][sb][1]) : 0.f;
            float p2 = (cb >= rs[mt][1] && cb <= hb[mt][1]) ? __expf(S[mt][sb][2]) : 0.f;
            float p3 = (cb + 1 >= rs[mt][1] && cb + 1 <= hb[mt][1]) ? __expf(S[mt][sb][3]) : 0.f;
            uint32_t h01 = cvt_h2(p0, p1), h23 = cvt_h2(p2, p3);
            PhF[mt][sb * 2 + 0] = h01;
            PhF[mt][sb * 2 + 1] = h23;
            float2 f01 = __half22float2(*reinterpret_cast<__half2*>(&h01));
            float2 f23 = __half22float2(*reinterpret_cast<__half2*>(&h23));
            l[mt][0] += f01.x + f01.y;
            l[mt][1] += f23.x + f23.y;
          }
      }

      // O += P_chunk V_chunk (16 kv rows), V frags shared across mt
#pragma unroll
      for (int d2 = 0; d2 < 8; d2++) {
        uint32_t voff = (uint32_t)nt2 * (16 * ROWB) + d2 * 32;
        uint32_t bh0, bh1, bh2, bh3;
        ldsm4t(vbase + voff, bh0, bh1, bh2, bh3);
        mma_f16(O[0][2 * d2], PhF[0], bh0, bh1);
        mma_f16(O[1][2 * d2], PhF[1], bh0, bh1);
        mma_f16(O[0][2 * d2 + 1], PhF[0], bh2, bh3);
        mma_f16(O[1][2 * d2 + 1], PhF[1], bh2, bh3);
      }
    }
  }

  // ---- epilogue: reduce row sums, normalize, store ---------------------------------
#pragma unroll
  for (int mt = 0; mt < 2; mt++) {
#pragma unroll
    for (int i = 0; i < 2; i++) {
      l[mt][i] += __shfl_xor_sync(0xffffffffu, l[mt][i], 1);
      l[mt][i] += __shfl_xor_sync(0xffffffffu, l[mt][i], 2);
    }
    const float inv0 = l[mt][0] > 0.f ? 1.0f / l[mt][0] : 0.f;
    const float inv1 = l[mt][1] > 0.f ? 1.0f / l[mt][1] : 0.f;
    if (rr[mt][0] < T) {
      float* o0 = out + ((size_t)rr[mt][0] * HEADS + h) * DIM + 2 * t;
#pragma unroll
      for (int nt = 0; nt < 16; nt++)
        *reinterpret_cast<float2*>(o0 + 8 * nt) =
            make_float2(O[mt][nt][0] * inv0, O[mt][nt][1] * inv0);
    }
    if (rr[mt][1] < T) {
      float* o1 = out + ((size_t)rr[mt][1] * HEADS + h) * DIM + 2 * t;
#pragma unroll
      for (int nt = 0; nt < 16; nt++)
        *reinterpret_cast<float2*>(o1 + 8 * nt) =
            make_float2(O[mt][nt][2] * inv1, O[mt][nt][3] * inv1);
    }
  }
}

extern "C" void kernel_launch(void* const* d_in, const int* in_sizes, int n_in,
                              void* d_out, int out_size) {
  const float* q = (const float*)d_in[0];
  const float* k = (const float*)d_in[1];
  const float* v = (const float*)d_in[2];
  const int* cu = (const int*)d_in[3];
  float* out = (float*)d_out;

  const int T = in_sizes[0] / (HEADS * DIM);
  const int B = in_sizes[3] - 1;

  // pre-pass: convert K/V to persistent fp16 arrays
  const int n4 = T * KVH * DIM / 4;
  conv_kv_kernel<<<(n4 + 255) / 256, 256>>>(
      reinterpret_cast<const float4*>(k), reinterpret_cast<const float4*>(v), n4);

  cudaFuncSetAttribute(fa_hmma_kernel, cudaFuncAttributeMaxDynamicSharedMemorySize,
                       SMEM_TOTAL);
  dim3 grid((T + BM - 1) / BM, HEADS);
  fa_hmma_kernel<<<grid, NTHREADS, SMEM_TOTAL>>>(q, cu, out, T, B);
}

// round 14
// speedup vs baseline: 1.1589x; 1.1589x over previous
#include <cuda_runtime.h>
#include <cuda_fp16.h>
#include <cstdint>

namespace {
constexpr int BM = 64, BN = 64, DIM = 128;
constexpr int NTHREADS = 128;
constexpr int HEADS = 32, KVH = 8, REP = HEADS / KVH;
constexpr int LD = 136;      // fp16 elems per smem row: 272B stride, conflict-free ldmatrix
constexpr int ROWB = LD * 2; // 272
// 1/sqrt(128) * log2(e): exp(s) == exp2(s') with s' computed from pre-scaled Q
constexpr float SCALE_L2E = 0.12751743136838648f;

constexpr int MAXT = 8192;

// smem: two buffers of [KH, VH]; Q staged through buffer 1 pre-loop
constexpr int TILEB = BN * ROWB;               // 17408
constexpr int BUFSZ = 2 * TILEB;               // 34816
constexpr int SMEM_TOTAL = 2 * BUFSZ;          // 69632 -> 3 CTAs/SM (208896 B)
}  // namespace

// persistent fp16 K/V (elem-pairs as uint32: low 16 = even elem)
__device__ uint32_t g_kh[MAXT * KVH * DIM / 2];
__device__ uint32_t g_vh[MAXT * KVH * DIM / 2];

__device__ __forceinline__ uint32_t smem_u32(const void* p) {
  uint32_t a;
  asm("{ .reg .u64 t; cvta.to.shared.u64 t, %1; cvt.u32.u64 %0, t; }" : "=r"(a) : "l"(p));
  return a;
}
__device__ __forceinline__ uint32_t cvt_h2(float a, float b) {
  uint32_t h;
  asm("cvt.rn.f16x2.f32 %0, %1, %2;" : "=r"(h) : "f"(b), "f"(a));  // low16=a, high16=b
  return h;
}
__device__ __forceinline__ float ex2(float x) {
  float y;
  asm("ex2.approx.ftz.f32 %0, %1;" : "=f"(y) : "f"(x));
  return y;
}
__device__ __forceinline__ void ldsm4(uint32_t a, uint32_t& r0, uint32_t& r1,
                                      uint32_t& r2, uint32_t& r3) {
  asm volatile("ldmatrix.sync.aligned.m8n8.x4.shared.b16 {%0,%1,%2,%3}, [%4];"
               : "=r"(r0), "=r"(r1), "=r"(r2), "=r"(r3) : "r"(a));
}
__device__ __forceinline__ void ldsm4t(uint32_t a, uint32_t& r0, uint32_t& r1,
                                       uint32_t& r2, uint32_t& r3) {
  asm volatile("ldmatrix.sync.aligned.m8n8.x4.trans.shared.b16 {%0,%1,%2,%3}, [%4];"
               : "=r"(r0), "=r"(r1), "=r"(r2), "=r"(r3) : "r"(a));
}
__device__ __forceinline__ void mma_f16(float* c, const uint32_t* a, uint32_t b0,
                                        uint32_t b1) {
  asm volatile(
      "mma.sync.aligned.m16n8k16.row.col.f32.f16.f16.f32 "
      "{%0,%1,%2,%3}, {%4,%5,%6,%7}, {%8,%9}, {%0,%1,%2,%3};"
      : "+f"(c[0]), "+f"(c[1]), "+f"(c[2]), "+f"(c[3])
      : "r"(a[0]), "r"(a[1]), "r"(a[2]), "r"(a[3]), "r"(b0), "r"(b1));
}
__device__ __forceinline__ void cp16(uint32_t dst, const uint32_t* src) {
  asm volatile(
      "{ .reg .u64 g; cvta.to.global.u64 g, %1; cp.async.cg.shared.global [%0], [g], 16; }"
      ::"r"(dst), "l"(src) : "memory");
}
#define CP_COMMIT() asm volatile("cp.async.commit_group;" ::: "memory")
#define CP_WAIT(n) asm volatile("cp.async.wait_group %0;" ::"n"(n) : "memory")

// ---------------- pre-pass: convert K and V to fp16 -------------------------
__global__ void conv_kv_kernel(const float4* __restrict__ k4,
                               const float4* __restrict__ v4, int n4) {
  int i = blockIdx.x * blockDim.x + threadIdx.x;
  if (i >= n4) return;
  float4 kv = k4[i], vv = v4[i];
  g_kh[i * 2] = cvt_h2(kv.x, kv.y);
  g_kh[i * 2 + 1] = cvt_h2(kv.z, kv.w);
  g_vh[i * 2] = cvt_h2(vv.x, vv.y);
  g_vh[i * 2 + 1] = cvt_h2(vv.z, vv.w);
}

// ---------------- main flash-attention kernel -------------------------------
__global__ __launch_bounds__(NTHREADS, 3)
void fa_hmma_kernel(const float* __restrict__ q, const int* __restrict__ cu,
                    float* __restrict__ out, int T, int B) {
  extern __shared__ __align__(16) char smem[];
  const uint32_t smb = smem_u32(smem);
  const int tid = threadIdx.x, lane = tid & 31, wid = tid >> 5;
  const int g = lane >> 2, t = lane & 3;
  const int q0 = blockIdx.x * BM, h = blockIdx.y, hk = h / REP;
  const int wrow = wid * 16;

  // ---- per-thread row bounds ---------------------------------------------------
  const int r0 = q0 + wrow + g, r1 = r0 + 8;
  int rs0 = 0, rs1 = 0, kv_lo = 0;
  for (int b = 1; b <= B; b++) {
    int e = cu[b];
    if (r0 >= e) rs0 = e;
    if (r1 >= e) rs1 = e;
    if (q0 >= e) kv_lo = e;
  }
  const int hb0 = (r0 < T) ? r0 : -1;
  const int hb1 = (r1 < T) ? r1 : -1;
  const int kv_hi = min(q0 + BM, T);

  // staging decomposition (16 cp16/thread per tile: both K and V)
  const int sc = tid & 15, srh = tid >> 4;  // srh in 0..7

  auto stage = [&](int c0, int buf) {
    uint32_t dbase = smb + buf * BUFSZ;
#pragma unroll
    for (int i = 0; i < 16; i++) {
      int a = i >> 3;
      int r = (i & 7) * 8 + srh;
      const uint32_t* src =
          (a ? g_vh : g_kh) + ((size_t)(c0 + r) * KVH + hk) * (DIM / 2) + sc * 4;
      cp16(dbase + a * TILEB + (uint32_t)r * ROWB + sc * 16, src);
    }
    CP_COMMIT();
  };

  // ---- prefetch tile 0 into buf0; stage Q via buf1; hoist Q frags to regs -------
  stage(kv_lo, 0);

  const float4* q4 = reinterpret_cast<const float4*>(q);
#pragma unroll
  for (int it = 0; it < 16; it++) {
    int idx = it * NTHREADS + tid;
    int row = idx >> 5, c4 = idx & 31;
    float4 val = make_float4(0.f, 0.f, 0.f, 0.f);
    int gr = q0 + row;
    if (gr < T) val = q4[((size_t)gr * HEADS + h) * 32 + c4];
    uint32_t hi0 = cvt_h2(val.x * SCALE_L2E, val.y * SCALE_L2E);
    uint32_t hi1 = cvt_h2(val.z * SCALE_L2E, val.w * SCALE_L2E);
    uint32_t off = (uint32_t)row * ROWB + c4 * 8;
    *reinterpret_cast<uint2*>(smem + BUFSZ + off) = make_uint2(hi0, hi1);
  }
  __syncthreads();

  const uint32_t qstg = smb + BUFSZ +
                        ((uint32_t)(wrow + (lane & 7) + (((lane >> 3) & 1) << 3)) * ROWB) +
                        ((lane >> 4) << 4);
  uint32_t qh[8][4];
#pragma unroll
  for (int kt = 0; kt < 8; kt++)
    ldsm4(qstg + kt * 32, qh[kt][0], qh[kt][1], qh[kt][2], qh[kt][3]);

  // ---- ldmatrix per-thread base offsets for K/V ----------------------------------
  const uint32_t krow = ((uint32_t)((lane & 7) + ((lane >> 4) << 3)) * ROWB) +
                        (((lane >> 3) & 1) << 4);
  const uint32_t vrow = ((uint32_t)((lane & 7) + (((lane >> 3) & 1) << 3)) * ROWB) +
                        ((lane >> 4) << 4);

  float O[16][4];
#pragma unroll
  for (int i = 0; i < 16; i++)
#pragma unroll
    for (int j = 0; j < 4; j++) O[i][j] = 0.f;
  float l0 = 0.f, l1 = 0.f;

  int bi = 0;
  for (int c0 = kv_lo; c0 < kv_hi; c0 += BN, bi++) {
    const int buf = bi & 1;
    const bool has_next = (c0 + BN) < kv_hi;

    __syncthreads();  // readers of buf^1 done (bi=0: Q frag reads done)
    if (has_next) { stage(c0 + BN, buf ^ 1); CP_WAIT(1); }
    else          { CP_WAIT(0); }
    __syncthreads();  // current buffer visible to all warps

    const uint32_t bb = smb + buf * BUFSZ;
    const uint32_t kbase = bb + krow;          // KH
    const uint32_t vbase = bb + TILEB + vrow;  // VH

    // ---- S' = Q K^T (1-pass fp16, Q frags in regs; S' = S*log2e) -------------------
    float S[8][4];
#pragma unroll
    for (int i = 0; i < 8; i++)
#pragma unroll
      for (int j = 0; j < 4; j++) S[i][j] = 0.f;

#pragma unroll
    for (int kt = 0; kt < 8; kt++) {
#pragma unroll
      for (int nt2 = 0; nt2 < 4; nt2++) {
        uint32_t bh0, bh1, bh2, bh3;
        uint32_t koff = (uint32_t)nt2 * (16 * ROWB) + kt * 32;
        ldsm4(kbase + koff, bh0, bh1, bh2, bh3);
        mma_f16(S[2 * nt2], qh[kt], bh0, bh1);
        mma_f16(S[2 * nt2 + 1], qh[kt], bh2, bh3);
      }
    }

    // ---- softmax: p = 2^(S'), mask, round to fp16; l-sums from fp32 p --------------
    uint32_t Ph[4][4];
    const bool safe = (r1 < T) && (c0 >= rs1) && (c0 + BN <= r0 + 1);
    if (__all_sync(0xffffffffu, safe)) {
#pragma unroll
      for (int nt = 0; nt < 8; nt++) {
        float p0 = ex2(S[nt][0]);
        float p1 = ex2(S[nt][1]);
        float p2 = ex2(S[nt][2]);
        float p3 = ex2(S[nt][3]);
        l0 += p0 + p1;
        l1 += p2 + p3;
        int ktp = nt >> 1, s2 = (nt & 1) * 2;
        Ph[ktp][s2 + 0] = cvt_h2(p0, p1);
        Ph[ktp][s2 + 1] = cvt_h2(p2, p3);
      }
    } else {
#pragma unroll
      for (int nt = 0; nt < 8; nt++) {
        int cb = c0 + 8 * nt + 2 * t;
        float p0 = (cb >= rs0 && cb <= hb0) ? ex2(S[nt][0]) : 0.f;
        float p1 = (cb + 1 >= rs0 && cb + 1 <= hb0) ? ex2(S[nt][1]) : 0.f;
        float p2 = (cb >= rs1 && cb <= hb1) ? ex2(S[nt][2]) : 0.f;
        float p3 = (cb + 1 >= rs1 && cb + 1 <= hb1) ? ex2(S[nt][3]) : 0.f;
        l0 += p0 + p1;
        l1 += p2 + p3;
        int ktp = nt >> 1, s2 = (nt & 1) * 2;
        Ph[ktp][s2 + 0] = cvt_h2(p0, p1);
        Ph[ktp][s2 + 1] = cvt_h2(p2, p3);
      }
    }

    // ---- O += P V (1-pass fp16), V frags via ldmatrix.trans -------------------------
#pragma unroll
    for (int ktp = 0; ktp < 4; ktp++) {
#pragma unroll
      for (int nt2 = 0; nt2 < 8; nt2++) {
        uint32_t voff = (uint32_t)ktp * (16 * ROWB) + nt2 * 32;
        uint32_t bh0, bh1, bh2, bh3;
        ldsm4t(vbase + voff, bh0, bh1, bh2, bh3);
        mma_f16(O[2 * nt2], Ph[ktp], bh0, bh1);
        mma_f16(O[2 * nt2 + 1], Ph[ktp], bh2, bh3);
      }
    }
  }

  // ---- epilogue: reduce row sums, normalize, store ---------------------------------
  l0 += __shfl_xor_sync(0xffffffffu, l0, 1);
  l0 += __shfl_xor_sync(0xffffffffu, l0, 2);
  l1 += __shfl_xor_sync(0xffffffffu, l1, 1);
  l1 += __shfl_xor_sync(0xffffffffu, l1, 2);
  const float inv0 = l0 > 0.f ? 1.0f / l0 : 0.f;
  const float inv1 = l1 > 0.f ? 1.0f / l1 : 0.f;

  if (r0 < T) {
    float* o0 = out + ((size_t)r0 * HEADS + h) * DIM + 2 * t;
#pragma unroll
    for (int nt = 0; nt < 16; nt++)
      *reinterpret_cast<float2*>(o0 + 8 * nt) = make_float2(O[nt][0] * inv0, O[nt][1] * inv0);
  }
  if (r1 < T) {
    float* o1 = out + ((size_t)r1 * HEADS + h) * DIM + 2 * t;
#pragma unroll
    for (int nt = 0; nt < 16; nt++)
      *reinterpret_cast<float2*>(o1 + 8 * nt) = make_float2(O[nt][2] * inv1, O[nt][3] * inv1);
  }
}

extern "C" void kernel_launch(void* const* d_in, const int* in_sizes, int n_in,
                              void* d_out, int out_size) {
  const float* q = (const float*)d_in[0];
  const float* k = (const float*)d_in[1];
  const float* v = (const float*)d_in[2];
  const int* cu = (const int*)d_in[3];
  float* out = (float*)d_out;

  const int T = in_sizes[0] / (HEADS * DIM);
  const int B = in_sizes[3] - 1;

  // pre-pass: convert K/V to persistent fp16 arrays
  const int n4 = T * KVH * DIM / 4;
  conv_kv_kernel<<<(n4 + 255) / 256, 256>>>(
      reinterpret_cast<const float4*>(k), reinterpret_cast<const float4*>(v), n4);

  cudaFuncSetAttribute(fa_hmma_kernel, cudaFuncAttributeMaxDynamicSharedMemorySize,
                       SMEM_TOTAL);
  dim3 grid((T + BM - 1) / BM, HEADS);
  fa_hmma_kernel<<<grid, NTHREADS, SMEM_TOTAL>>>(q, cu, out, T, B);
}